// round 2
// baseline (speedup 1.0000x reference)
#include <cuda_runtime.h>
#include <stdint.h>

#define Mv 128          // variants
#define Nv 256          // positions
#define Cv 22           // classes
#define TILE (Cv*Cv)    // 484 floats per (i,j) tile
#define JC 8            // j per pipeline chunk
#define NCHUNK (Nv/JC)  // 32
#define NSTAGES 3
#define STAGE_FLOATS (JC*TILE)   // 3872 floats = 15488 B
#define CHALF 11

// [j][m] byte layout: coalesced per-j reads (32 consecutive bytes per warp)
__device__ __align__(16) unsigned char g_dsel[Nv*Mv];
// per-position pooled-delta partials: g_part[i][m]
__device__ float g_part[Nv*Mv];

// ---------------------------------------------------------------------------
__global__ void prep_kernel(const int* __restrict__ variant) {
    int idx = blockIdx.x * blockDim.x + threadIdx.x;   // flat over [m][j]
    if (idx < Mv * Nv) {
        int m = idx >> 8;           // /Nv
        int j = idx & (Nv - 1);
        g_dsel[j * Mv + m] = (unsigned char)variant[idx];
    }
}

// ---------------------------------------------------------------------------
__device__ __forceinline__ void issue_chunk(const float* gbase, int k, int t,
                                            float (*sE)[STAGE_FLOATS]) {
    if (k < NCHUNK) {
        const char* src = (const char*)(gbase + (size_t)k * STAGE_FLOATS);
        uint32_t dst = (uint32_t)__cvta_generic_to_shared(&sE[k % NSTAGES][0]);
        #pragma unroll 1
        for (int u = t; u < STAGE_FLOATS / 4; u += 256) {
            asm volatile("cp.async.cg.shared.global [%0], [%1], 16;\n"
                         :: "r"(dst + u * 16), "l"(src + (size_t)u * 16));
        }
    }
    asm volatile("cp.async.commit_group;\n");
}

__global__ __launch_bounds__(256) void potts_kernel(
    const float* __restrict__ eij,
    const float* __restrict__ ei,
    const float* __restrict__ mask_vec,
    const float* __restrict__ vmask,
    const float* __restrict__ sigma,
    float* __restrict__ motifs,     // [Mv, Nv, Cv]
    float* __restrict__ logits)     // [Mv, Nv]
{
    __shared__ __align__(16) float sE[NSTAGES][STAGE_FLOATS];
    __shared__ float smask[32];
    __shared__ float sei[Cv];
    __shared__ float slog[Mv];

    const int i    = blockIdx.x;
    const int t    = threadIdx.x;
    const int m    = t & (Mv - 1);
    const int half = t >> 7;
    const int c0   = half * CHALF;

    if (t < Cv) {
        smask[t] = mask_vec[t];
        sei[t]   = ei[i * Cv + t];
    }

    const float* gbase = eij + (size_t)i * (Nv * TILE);

    float acc[CHALF];
    #pragma unroll
    for (int cc = 0; cc < CHALF; ++cc) acc[cc] = 0.0f;

    // prime 2 stages
    issue_chunk(gbase, 0, t, sE);
    issue_chunk(gbase, 1, t, sE);

    for (int k = 0; k < NCHUNK; ++k) {
        asm volatile("cp.async.wait_group %0;\n" :: "n"(NSTAGES - 2));
        __syncthreads();   // chunk k ready for all; stage (k-1) fully consumed by all

        // ---- prefetch the 8 class ids (MLP=8) and their mask scales ----
        int d8[JC];
        const int jbase = k * JC;
        #pragma unroll
        for (int jj = 0; jj < JC; ++jj)
            d8[jj] = g_dsel[(jbase + jj) * Mv + m];
        float s8[JC];
        #pragma unroll
        for (int jj = 0; jj < JC; ++jj)
            s8[jj] = smask[d8[jj]];

        const float* buf = sE[k % NSTAGES];
        #pragma unroll
        for (int jj = 0; jj < JC; ++jj) {
            const float* row = buf + jj * TILE + c0 * Cv + d8[jj];
            const float s = s8[jj];
            #pragma unroll
            for (int cc = 0; cc < CHALF; ++cc)
                acc[cc] = fmaf(s, row[cc * Cv], acc[cc]);   // conflict-free LDS
        }

        // overwrites stage (k-1)%3 — safe: its consumption ended before the
        // __syncthreads at the top of THIS iteration.
        issue_chunk(gbase, k + 2, t, sE);
    }

    // ---- epilogue: motifs, logits, pooled-delta partial ----
    const int vmi = g_dsel[i * Mv + m];
    float* mout = motifs + ((size_t)m * Nv + i) * Cv;
    float myl = 0.0f;
    bool own = (vmi >= c0) && (vmi < c0 + CHALF);
    #pragma unroll
    for (int cc = 0; cc < CHALF; ++cc) {
        const int c = c0 + cc;
        const float v = acc[cc] + sei[c];
        mout[c] = v;
        if (c == vmi) myl = v;
    }
    if (own) slog[m] = myl;
    __syncthreads();

    if (t < Mv) {
        const float lm = slog[t];
        logits[t * Nv + i] = lm;
        const float w = vmask[t * Nv + i] * vmask[i];
        g_part[i * Mv + t] = (lm - slog[0]) * w * sigma[0];
    }
}

// ---------------------------------------------------------------------------
// deterministic reduce over i: vlog[m] = sum_i g_part[i][m]
__global__ void reduce_kernel(float* __restrict__ vlog) {
    __shared__ float spart[Mv];
    const int t = threadIdx.x;          // 256 threads
    const int m = t & (Mv - 1);
    const int h = t >> 7;
    float s = 0.0f;
    #pragma unroll 4
    for (int i = h * (Nv / 2); i < (h + 1) * (Nv / 2); ++i)
        s += g_part[i * Mv + m];        // coalesced
    if (h == 0) spart[m] = s;
    __syncthreads();
    if (h == 1) vlog[m] = spart[m] + s;
}

__global__ void nop_kernel() {}

// ---------------------------------------------------------------------------
extern "C" void kernel_launch(void* const* d_in, const int* in_sizes, int n_in,
                              void* d_out, int out_size) {
    int idx_eij = 2, idx_ei = 3, idx_mask = 4, idx_sigma = 5;
    int big1 = 0, big2 = 1;
    {
        int b1 = -1, b2 = -1;
        for (int q = 0; q < n_in; ++q) {
            int s = in_sizes[q];
            if (s == Nv * Nv * Cv * Cv)      idx_eij = q;
            else if (s == Nv * Cv)           idx_ei = q;
            else if (s == Cv)                idx_mask = q;
            else if (s == 1)                 idx_sigma = q;
            else if (s == Mv * Nv) { if (b1 < 0) b1 = q; else b2 = q; }
        }
        if (b1 >= 0) big1 = b1;
        if (b2 >= 0) big2 = b2;
    }

    const int*   variant = (const int*)d_in[big1];
    const float* vmask   = (const float*)d_in[big2];
    const float* eij     = (const float*)d_in[idx_eij];
    const float* ei      = (const float*)d_in[idx_ei];
    const float* maskv   = (const float*)d_in[idx_mask];
    const float* sigma   = (const float*)d_in[idx_sigma];

    float* out    = (float*)d_out;
    float* motifs = out;                               // [128,256,22]
    float* logits = out + (size_t)Mv * Nv * Cv;        // [128,256]
    float* vlog   = logits + (size_t)Mv * Nv;          // [128,1]

    prep_kernel<<<(Mv * Nv + 255) / 256, 256>>>(variant);
    potts_kernel<<<Nv, 256>>>(eij, ei, maskv, vmask, sigma, motifs, logits);
    reduce_kernel<<<1, 256>>>(vlog);
    nop_kernel<<<1, 32>>>();
}